// round 12
// baseline (speedup 1.0000x reference)
#include <cuda_runtime.h>
#include <cstdint>

#define COLS 8192
#define COLS4 2048
#define ROWS 1024
#define SCALE 0.75f
#define QTR 2048              // floats per quarter-row
#define PAIR_OFF 512          // row pairing distance

// Scratch (no allocation allowed). 32B-aligned for LDG.256.
__device__ __align__(32) float g_wtotal[COLS];

// LDG.256 + evict_last (x stream: L2-resident across graph replays).
__device__ __forceinline__ void ldg256_el(const float* p, float4& a, float4& b) {
    unsigned r0, r1, r2, r3, r4, r5, r6, r7;
    asm volatile("ld.global.nc.L2::evict_last.v8.b32 {%0,%1,%2,%3,%4,%5,%6,%7}, [%8];"
        : "=r"(r0), "=r"(r1), "=r"(r2), "=r"(r3),
          "=r"(r4), "=r"(r5), "=r"(r6), "=r"(r7)
        : "l"(p));
    a.x = __uint_as_float(r0); a.y = __uint_as_float(r1);
    a.z = __uint_as_float(r2); a.w = __uint_as_float(r3);
    b.x = __uint_as_float(r4); b.y = __uint_as_float(r5);
    b.z = __uint_as_float(r6); b.w = __uint_as_float(r7);
}
// Plain LDG.256 (w: L1/L2-hot).
__device__ __forceinline__ void ldg256(const float* p, float4& a, float4& b) {
    unsigned r0, r1, r2, r3, r4, r5, r6, r7;
    asm volatile("ld.global.nc.v8.b32 {%0,%1,%2,%3,%4,%5,%6,%7}, [%8];"
        : "=r"(r0), "=r"(r1), "=r"(r2), "=r"(r3),
          "=r"(r4), "=r"(r5), "=r"(r6), "=r"(r7)
        : "l"(p));
    a.x = __uint_as_float(r0); a.y = __uint_as_float(r1);
    a.z = __uint_as_float(r2); a.w = __uint_as_float(r3);
    b.x = __uint_as_float(r4); b.y = __uint_as_float(r5);
    b.z = __uint_as_float(r6); b.w = __uint_as_float(r7);
}

// ---------------- Kernel 1: w_total[c] = sum_g wsums[g][c] ----------------
__global__ __launch_bounds__(256) void reduce_w_kernel(const float* __restrict__ wsums) {
    const int lcol  = threadIdx.x & 31;
    const int chunk = threadIdx.x >> 5;               // 0..7, 4 groups each
    const int c4    = blockIdx.x * 32 + lcol;

    const float4* __restrict__ w4 = reinterpret_cast<const float4*>(wsums);
    float4 s = make_float4(0.f, 0.f, 0.f, 0.f);
#pragma unroll
    for (int g = 0; g < 4; ++g) {
        float4 v = w4[(size_t)(chunk * 4 + g) * COLS4 + c4];
        s.x += v.x; s.y += v.y; s.z += v.z; s.w += v.w;
    }

    __shared__ float4 sm[8][32];
    sm[chunk][lcol] = s;
    __syncthreads();

    if (threadIdx.x < 32) {
        float4 r = make_float4(0.f, 0.f, 0.f, 0.f);
#pragma unroll
        for (int c = 0; c < 8; ++c) {
            float4 v = sm[c][threadIdx.x];
            r.x += v.x; r.y += v.y; r.z += v.z; r.w += v.w;
        }
        reinterpret_cast<float4*>(g_wtotal)[c4] = r;
    }
}

// ---------------- Kernel 2: row-paired warp-per-quarter matvec + PDL ----------------
// Grid 256 x 256 thr (8 warps). Warp W=b*8+wid owns quarter j=W&3 of rows
// r=W>>2 and r+512 (same w chunk serves both). 8-iter loop, 2 x-streams
// prefetched 2 ahead -> 16-deep load pipeline. First 2 iterations of x are
// issued BEFORE cudaGridDependencySynchronize() so reduce_w overlaps them.
__global__ __launch_bounds__(256, 3) void dot_pair_kernel(const float* __restrict__ x,
                                                          float* __restrict__ out) {
    const int t   = threadIdx.x;
    const int wid = t >> 5;
    const int lid = t & 31;
    const int W   = blockIdx.x * 8 + wid;
    const int r   = W >> 2;
    const int j   = W & 3;

    const float* __restrict__ xr1 = x + (size_t)r * COLS + j * QTR + lid * 8;
    const float* __restrict__ xr2 = xr1 + (size_t)PAIR_OFF * COLS;
    const float* __restrict__ wr  = g_wtotal + j * QTR + lid * 8;

    // Prefetch iterations 0,1 of both x streams (no w dependency yet).
    float4 pa[2][2], pb[2][2];
    ldg256_el(xr1 + 0 * 256, pa[0][0], pa[0][1]);
    ldg256_el(xr2 + 0 * 256, pb[0][0], pb[0][1]);
    ldg256_el(xr1 + 1 * 256, pa[1][0], pa[1][1]);
    ldg256_el(xr2 + 1 * 256, pb[1][0], pb[1][1]);

    // Wait for reduce_w's writes to g_wtotal (PDL dependency).
    cudaGridDependencySynchronize();

    float u0 = 0.f, u1 = 0.f, v0 = 0.f, v1 = 0.f;
#pragma unroll
    for (int i = 0; i < 8; ++i) {
        const int slot = i & 1;
        float4 w0, w1;
        ldg256(wr + i * 256, w0, w1);
        const float4 a0 = pa[slot][0], a1 = pa[slot][1];
        const float4 b0 = pb[slot][0], b1 = pb[slot][1];
        if (i + 2 < 8) {
            ldg256_el(xr1 + (i + 2) * 256, pa[slot][0], pa[slot][1]);
            ldg256_el(xr2 + (i + 2) * 256, pb[slot][0], pb[slot][1]);
        }
        u0 = fmaf(a0.x, w0.x, u0); u1 = fmaf(a0.y, w0.y, u1);
        u0 = fmaf(a0.z, w0.z, u0); u1 = fmaf(a0.w, w0.w, u1);
        u0 = fmaf(a1.x, w1.x, u0); u1 = fmaf(a1.y, w1.y, u1);
        u0 = fmaf(a1.z, w1.z, u0); u1 = fmaf(a1.w, w1.w, u1);
        v0 = fmaf(b0.x, w0.x, v0); v1 = fmaf(b0.y, w0.y, v1);
        v0 = fmaf(b0.z, w0.z, v0); v1 = fmaf(b0.w, w0.w, v1);
        v0 = fmaf(b1.x, w1.x, v0); v1 = fmaf(b1.y, w1.y, v1);
        v0 = fmaf(b1.z, w1.z, v0); v1 = fmaf(b1.w, w1.w, v1);
    }
    float u = u0 + u1;     // row r partial
    float v = v0 + v1;     // row r+512 partial

#pragma unroll
    for (int o = 16; o > 0; o >>= 1) {
        u += __shfl_xor_sync(0xFFFFFFFFu, u, o);
        v += __shfl_xor_sync(0xFFFFFFFFu, v, o);
    }

    __shared__ float red[2][8];
    if (lid == 0) { red[0][wid] = u; red[1][wid] = v; }
    __syncthreads();

    if (t < 4) {
        const int half = t >> 1;            // 0: rows 2b..., 1: +512
        const int sub  = t & 1;
        const float s = (red[half][sub * 4 + 0] + red[half][sub * 4 + 1])
                      + (red[half][sub * 4 + 2] + red[half][sub * 4 + 3]);
        out[blockIdx.x * 2 + sub + half * PAIR_OFF] = s * SCALE;
    }
}

extern "C" void kernel_launch(void* const* d_in, const int* in_sizes, int n_in,
                              void* d_out, int out_size) {
    const float* x     = (const float*)d_in[0];  // [1024, 8192] f32
    const float* wsums = (const float*)d_in[1];  // [32, 8192] f32
    float* out         = (float*)d_out;          // [1024, 1] f32

    reduce_w_kernel<<<COLS4 / 32, 256>>>(wsums);

    // PDL launch: dot starts while reduce_w drains; gridDepSync gates w reads.
    cudaLaunchConfig_t cfg = {};
    cfg.gridDim  = dim3(256, 1, 1);
    cfg.blockDim = dim3(256, 1, 1);
    cfg.dynamicSmemBytes = 0;
    cfg.stream = 0;
    cudaLaunchAttribute at[1];
    at[0].id = cudaLaunchAttributeProgrammaticStreamSerialization;
    at[0].val.programmaticStreamSerializationAllowed = 1;
    cfg.attrs = at;
    cfg.numAttrs = 1;
    cudaLaunchKernelEx(&cfg, dot_pair_kernel, x, (float*)d_out);
}